// round 3
// baseline (speedup 1.0000x reference)
#include <cuda_runtime.h>

// bMomentumLIF: x [B=64, T=64, F=8192] fp32 -> spikes [B, T, F] fp32.
// R3: float2 per thread + 4-deep prefetch pipeline (double per-warp MLP to get
// off the DRAM-latency knee: 48 warps x 4 x 256B ~ 85 B/cyc/SM latency tolerance
// vs ~43 needed). Streaming cache hints on both paths.

#define B_DIM 64
#define T_DIM 64
#define F_DIM 8192
#define F2    (F_DIM / 2)   // 4096 float2 lanes per (b,t) row
#define PF    4             // prefetch depth

__global__ __launch_bounds__(128, 12)
void lif_kernel(const float2* __restrict__ x,
                const float* __restrict__ p_mom,
                const float* __restrict__ p_lamb,
                const float* __restrict__ p_th,
                float2* __restrict__ out)
{
    const int f2 = blockIdx.x * blockDim.x + threadIdx.x;  // 0..F2-1
    const int b  = blockIdx.y;

    const float mt  = p_mom[0];
    const float lb  = p_lamb[0];
    const float th  = p_th[0];
    const float omt = 1.0f - mt;
    const float olb = 1.0f - lb;

    const float2* xp = x   + (size_t)b * T_DIM * F2 + (size_t)f2;
    float2*       op = out + (size_t)b * T_DIM * F2 + (size_t)f2;

    float2 u_last = make_float2(0.f, 0.f);
    float2 m      = make_float2(0.f, 0.f);

    // 4-deep prefetch pipeline (addresses independent of the recurrence)
    float2 pf0 = __ldcs(xp + 0 * F2);
    float2 pf1 = __ldcs(xp + 1 * F2);
    float2 pf2 = __ldcs(xp + 2 * F2);
    float2 pf3 = __ldcs(xp + 3 * F2);

    #pragma unroll 8
    for (int t = 0; t < T_DIM; ++t) {
        float2 xn;
        if (t + PF < T_DIM) xn = __ldcs(xp + (size_t)(t + PF) * F2);

        float2 s;
        // lane x
        {
            float u  = fmaf(u_last.x, 0.5f, pf0.x);
            float sp = (u - th >= 0.0f) ? 1.0f : 0.0f;
            float mn = fmaf(mt, m.x, omt * (u - u_last.x));
            m.x = mn;
            u_last.x = fmaf(u, lb, mn * olb) * (1.0f - sp);
            s.x = sp;
        }
        // lane y
        {
            float u  = fmaf(u_last.y, 0.5f, pf0.y);
            float sp = (u - th >= 0.0f) ? 1.0f : 0.0f;
            float mn = fmaf(mt, m.y, omt * (u - u_last.y));
            m.y = mn;
            u_last.y = fmaf(u, lb, mn * olb) * (1.0f - sp);
            s.y = sp;
        }

        __stcs(op + (size_t)t * F2, s);

        // shift pipeline
        pf0 = pf1;
        pf1 = pf2;
        pf2 = pf3;
        pf3 = xn;
    }
}

extern "C" void kernel_launch(void* const* d_in, const int* in_sizes, int n_in,
                              void* d_out, int out_size)
{
    const float2* x    = (const float2*)d_in[0];
    const float*  mom  = (const float*)d_in[1];
    const float*  lamb = (const float*)d_in[2];
    const float*  th   = (const float*)d_in[3];
    float2*       out  = (float2*)d_out;

    dim3 block(128);
    dim3 grid(F2 / 128, B_DIM);   // (32, 64) = 2048 blocks
    lif_kernel<<<grid, block>>>(x, mom, lamb, th, out);
}

// round 4
// speedup vs baseline: 1.2448x; 1.2448x over previous
#include <cuda_runtime.h>

// bMomentumLIF: x [B=64, T=64, F=8192] fp32 -> spikes [B, T, F] fp32.
// R4: float2 + 3-deep prefetch, register-capped to 36 via launch_bounds(128,14)
// so ALL 2048 blocks stay co-resident in one wave (R3's 40-reg build split into
// 2 waves and tanked occupancy). MLP=3 per warp: ~73 B/cyc/SM latency tolerance
// vs ~43 needed at the LTS cap.

#define B_DIM 64
#define T_DIM 64
#define F_DIM 8192
#define F2    (F_DIM / 2)   // 4096 float2 lanes per (b,t) row
#define PF    3             // prefetch depth

__global__ __launch_bounds__(128, 14)
void lif_kernel(const float2* __restrict__ x,
                const float* __restrict__ p_mom,
                const float* __restrict__ p_lamb,
                const float* __restrict__ p_th,
                float2* __restrict__ out)
{
    const int f2 = blockIdx.x * blockDim.x + threadIdx.x;  // 0..F2-1
    const int b  = blockIdx.y;

    const float mt  = p_mom[0];
    const float lb  = p_lamb[0];
    const float th  = p_th[0];
    const float omt = 1.0f - mt;
    const float olb = 1.0f - lb;

    const float2* xp = x   + (size_t)b * T_DIM * F2 + (size_t)f2;
    float2*       op = out + (size_t)b * T_DIM * F2 + (size_t)f2;

    float2 u_last = make_float2(0.f, 0.f);
    float2 m      = make_float2(0.f, 0.f);

    // 3-deep prefetch pipeline (addresses independent of the recurrence)
    float2 pf0 = __ldcs(xp + 0 * F2);
    float2 pf1 = __ldcs(xp + 1 * F2);
    float2 pf2 = __ldcs(xp + 2 * F2);

    #pragma unroll 8
    for (int t = 0; t < T_DIM; ++t) {
        float2 xn;
        if (t + PF < T_DIM) xn = __ldcs(xp + (size_t)(t + PF) * F2);

        float2 s;
        // lane x
        {
            float u  = fmaf(u_last.x, 0.5f, pf0.x);
            float sp = (u - th >= 0.0f) ? 1.0f : 0.0f;
            float mn = fmaf(mt, m.x, omt * (u - u_last.x));
            m.x = mn;
            u_last.x = fmaf(u, lb, mn * olb) * (1.0f - sp);
            s.x = sp;
        }
        // lane y
        {
            float u  = fmaf(u_last.y, 0.5f, pf0.y);
            float sp = (u - th >= 0.0f) ? 1.0f : 0.0f;
            float mn = fmaf(mt, m.y, omt * (u - u_last.y));
            m.y = mn;
            u_last.y = fmaf(u, lb, mn * olb) * (1.0f - sp);
            s.y = sp;
        }

        __stcs(op + (size_t)t * F2, s);

        // shift pipeline
        pf0 = pf1;
        pf1 = pf2;
        pf2 = xn;
    }
}

extern "C" void kernel_launch(void* const* d_in, const int* in_sizes, int n_in,
                              void* d_out, int out_size)
{
    const float2* x    = (const float2*)d_in[0];
    const float*  mom  = (const float*)d_in[1];
    const float*  lamb = (const float*)d_in[2];
    const float*  th   = (const float*)d_in[3];
    float2*       out  = (float2*)d_out;

    dim3 block(128);
    dim3 grid(F2 / 128, B_DIM);   // (32, 64) = 2048 blocks
    lif_kernel<<<grid, block>>>(x, mom, lamb, th, out);
}

// round 5
// speedup vs baseline: 1.3005x; 1.0448x over previous
#include <cuda_runtime.h>

// bMomentumLIF: x [B=64, T=64, F=8192] fp32 -> spikes [B, T, F] fp32.
// R5: R2 config (float2, PF=2, one co-resident wave) +
//  - 64-thread blocks (4096 blocks -> 27.7/SM, wave imbalance 7.4% -> 3.6%)
//  - select-based epilogue (u_next = d>=0 ? 0 : fma(...)) saves 2 FP ops/lane/t
// We are at ~84% of HBM spec (268MB / 39.7us) -- chasing the last few percent.

#define B_DIM 64
#define T_DIM 64
#define F_DIM 8192
#define F2    (F_DIM / 2)   // 4096 float2 lanes per (b,t) row
#define PF    2             // prefetch depth (R4 showed deeper buys nothing)

__global__ __launch_bounds__(64, 28)
void lif_kernel(const float2* __restrict__ x,
                const float* __restrict__ p_mom,
                const float* __restrict__ p_lamb,
                const float* __restrict__ p_th,
                float2* __restrict__ out)
{
    const int f2 = blockIdx.x * 64 + threadIdx.x;  // 0..F2-1
    const int b  = blockIdx.y;

    const float mt  = p_mom[0];
    const float lb  = p_lamb[0];
    const float th  = p_th[0];
    const float omt = 1.0f - mt;
    const float olb = 1.0f - lb;

    const float2* xp = x   + (size_t)b * T_DIM * F2 + (size_t)f2;
    float2*       op = out + (size_t)b * T_DIM * F2 + (size_t)f2;

    float2 u_last = make_float2(0.f, 0.f);
    float2 m      = make_float2(0.f, 0.f);

    // 2-deep prefetch pipeline (addresses independent of the recurrence)
    float2 xi0 = __ldcs(xp);
    float2 xi1 = __ldcs(xp + F2);

    #pragma unroll 8
    for (int t = 0; t < T_DIM; ++t) {
        float2 xn;
        if (t + PF < T_DIM) xn = __ldcs(xp + (size_t)(t + PF) * F2);

        float2 s;
        // lane x
        {
            float u  = fmaf(u_last.x, 0.5f, xi0.x);
            float d  = u - th;
            float mn = fmaf(mt, m.x, omt * (u - u_last.x));
            m.x = mn;
            float v  = fmaf(u, lb, mn * olb);
            u_last.x = (d >= 0.0f) ? 0.0f : v;
            s.x      = (d >= 0.0f) ? 1.0f : 0.0f;
        }
        // lane y
        {
            float u  = fmaf(u_last.y, 0.5f, xi0.y);
            float d  = u - th;
            float mn = fmaf(mt, m.y, omt * (u - u_last.y));
            m.y = mn;
            float v  = fmaf(u, lb, mn * olb);
            u_last.y = (d >= 0.0f) ? 0.0f : v;
            s.y      = (d >= 0.0f) ? 1.0f : 0.0f;
        }

        __stcs(op + (size_t)t * F2, s);

        xi0 = xi1;
        xi1 = xn;
    }
}

extern "C" void kernel_launch(void* const* d_in, const int* in_sizes, int n_in,
                              void* d_out, int out_size)
{
    const float2* x    = (const float2*)d_in[0];
    const float*  mom  = (const float*)d_in[1];
    const float*  lamb = (const float*)d_in[2];
    const float*  th   = (const float*)d_in[3];
    float2*       out  = (float2*)d_out;

    dim3 block(64);
    dim3 grid(F2 / 64, B_DIM);   // (64, 64) = 4096 blocks
    lif_kernel<<<grid, block>>>(x, mom, lamb, th, out);
}